// round 17
// baseline (speedup 1.0000x reference)
#include <cuda_runtime.h>
#include <cuda_fp16.h>
#include <cstdint>

#define S_  2048
#define D_  64
#define NBH 32
#define TQ  128
#define TK  128
#define NKT (S_/TK)
#define NQT (S_/TQ)
#define PH  72            // padded smem row stride in halves (144B)
#define RB  144           // row stride bytes

// smem: K double-buffered, V single-buffered
#define KB0 0
#define KB1 18432
#define VB  36864
#define SMEM_BYTES 55296  // 3 CTAs/SM (regs ~85 also cap at 3)

#define NELEM (NBH * S_ * D_)
__device__ __half g_q16[NELEM];   // q pre-scaled by 0.125*log2e
__device__ __half g_k16[NELEM];
__device__ __half g_v16[NELEM];
// unnormalized p = 2^(q.k), fp16, HMMA A-fragment layout:
// index = (((bh*NQT + qt)*NKT + kt)*8 + chunk)*256 + tid   (uint4 each)
#define PCNT (NBH * NQT * NKT * 8 * 256)
__device__ uint4  g_p[PCNT];

__device__ __forceinline__ uint32_t smem_u32(const void* p) {
    uint32_t a;
    asm("{ .reg .u64 t; cvta.to.shared.u64 t, %1; cvt.u32.u64 %0, t; }"
        : "=r"(a) : "l"(p));
    return a;
}
__device__ __forceinline__ void ldsm4(uint32_t a, uint32_t r[4]) {
    asm volatile("ldmatrix.sync.aligned.m8n8.x4.shared.b16 {%0,%1,%2,%3}, [%4];"
        : "=r"(r[0]), "=r"(r[1]), "=r"(r[2]), "=r"(r[3]) : "r"(a));
}
__device__ __forceinline__ void ldsm4t(uint32_t a, uint32_t r[4]) {
    asm volatile("ldmatrix.sync.aligned.m8n8.x4.trans.shared.b16 {%0,%1,%2,%3}, [%4];"
        : "=r"(r[0]), "=r"(r[1]), "=r"(r[2]), "=r"(r[3]) : "r"(a));
}
__device__ __forceinline__ void mmah(float c[4], const uint32_t a[4],
                                     const uint32_t b0, const uint32_t b1) {
    asm volatile("mma.sync.aligned.m16n8k16.row.col.f32.f16.f16.f32 "
        "{%0,%1,%2,%3}, {%4,%5,%6,%7}, {%8,%9}, {%0,%1,%2,%3};"
        : "+f"(c[0]), "+f"(c[1]), "+f"(c[2]), "+f"(c[3])
        : "r"(a[0]), "r"(a[1]), "r"(a[2]), "r"(a[3]), "r"(b0), "r"(b1));
}
__device__ __forceinline__ uint32_t packh2(float x, float y) {
    __half2 h = __floats2half2_rn(x, y);
    return *(uint32_t*)&h;
}
__device__ __forceinline__ float ex2f(float x) {
    float r;
    asm("ex2.approx.f32 %0, %1;" : "=f"(r) : "f"(x));
    return r;
}
// streaming (evict-first) global accesses for write-once / read-once data
__device__ __forceinline__ void stg_cs_u4(uint4* p, uint4 v) {
    asm volatile("st.global.cs.v4.u32 [%0], {%1,%2,%3,%4};"
        :: "l"(p), "r"(v.x), "r"(v.y), "r"(v.z), "r"(v.w) : "memory");
}
__device__ __forceinline__ uint4 ldg_cs_u4(const uint4* p) {
    uint4 v;
    asm volatile("ld.global.cs.v4.u32 {%0,%1,%2,%3}, [%4];"
        : "=r"(v.x), "=r"(v.y), "=r"(v.z), "=r"(v.w) : "l"(p));
    return v;
}
__device__ __forceinline__ void stg_cs_f2(float* p, float a, float b) {
    asm volatile("st.global.cs.v2.f32 [%0], {%1,%2};"
        :: "l"(p), "f"(a), "f"(b) : "memory");
}
#define CPA(d, s) asm volatile("cp.async.cg.shared.global [%0], [%1], 16;" \
                               :: "r"(d), "l"(s) : "memory")
#define CPC()     asm volatile("cp.async.commit_group;" ::: "memory")
#define CPW(n)    asm volatile("cp.async.wait_group %0;" :: "n"(n) : "memory")
// FIFO ledger: entry of iter kt pending = {K(kt), V(kt), K(kt+1)}.
// CPW(1) completes K(kt) and V(kt); last iteration drains everything.
#define CPW_ITER(kt) do { if ((kt) + 1 < NKT) { CPW(1); } else { CPW(0); } } while (0)

__device__ __forceinline__ void fetch_tile(uint32_t sdst, const __half* g, int tid) {
    #pragma unroll
    for (int i = 0; i < 4; i++) {
        int idx = i * 256 + tid;
        int row = idx >> 3, ch = idx & 7;
        CPA(sdst + (uint32_t)(row * RB + ch * 16),
            (const char*)g + (size_t)row * 128 + ch * 16);
    }
}

// ------------------- preconvert: fp32 -> fp16 -------------------
__global__ __launch_bounds__(256) void conv16(
    const float* __restrict__ q, const float* __restrict__ k,
    const float* __restrict__ v)
{
    int i = (blockIdx.x * 256 + threadIdx.x) * 4;
    const float* src; __half* dst; float sc;
    if (blockIdx.y == 0)      { src = q; dst = g_q16; sc = 0.125f * 1.44269504f; }
    else if (blockIdx.y == 1) { src = k; dst = g_k16; sc = 1.0f; }
    else                      { src = v; dst = g_v16; sc = 1.0f; }
    float4 x = *(const float4*)(src + i);
    uint2 o;
    o.x = packh2(x.x * sc, x.y * sc);
    o.y = packh2(x.z * sc, x.w * sc);
    *(uint2*)(dst + i) = o;
}

// ---- fused attention: phase B = QK + exp + p-store + AV; phase C = pure stream ----
__global__ __launch_bounds__(256, 3) void attn_fused(
    float* __restrict__ out, float* __restrict__ attn)
{
    extern __shared__ char sm[];
    const uint32_t sb = smem_u32(sm);
    const int tid = threadIdx.x;
    const int lane = tid & 31;
    const int w = tid >> 5;
    const int m0 = w * 16;
    const int bh = blockIdx.y;
    const int qt = blockIdx.x;
    const int qrow0 = qt * TQ;
    const size_t base = (size_t)bh * S_ * D_;
    const int g8 = lane >> 3;
    const uint32_t koff = (uint32_t)((((g8 >> 1) * 8 + (lane & 7)) * PH +
                                     (g8 & 1) * 8) * 2);
    const uint32_t voff = sb + VB +
        (uint32_t)((((lane & 7) + ((lane >> 3) & 1) * 8) * PH) * 2 + (lane >> 4) * 16);
    const __half* kg = g_k16 + base;
    const __half* vg = g_v16 + base;
    uint4* pbase = g_p + (size_t)((bh * NQT + qt) * NKT) * 8 * 256 + tid;

    // ---- prologue: Q -> KB0, fragments ----
    fetch_tile(sb + KB0, g_q16 + base + (size_t)qrow0 * D_, tid); CPC();
    CPW(0);
    __syncthreads();
    uint32_t aq[4][4];
    {
        int row = lane & 15;
        int colh = (lane >> 4) << 3;
        #pragma unroll
        for (int ks = 0; ks < 4; ks++)
            ldsm4(sb + KB0 + (uint32_t)(((m0 + row) * PH + ks * 16 + colh) * 2),
                  aq[ks]);
    }
    __syncthreads();

    // groups (FIFO): K0, V0, K1
    fetch_tile(sb + KB0, kg, tid);              CPC();
    fetch_tile(sb + VB,  vg, tid);              CPC();
    fetch_tile(sb + KB1, kg + 128 * D_, tid);   CPC();

    float oacc[8][4];
    #pragma unroll
    for (int d = 0; d < 8; d++)
        #pragma unroll
        for (int i = 0; i < 4; i++) oacc[d][i] = 0.f;
    float rs0 = 0.f, rs1 = 0.f;

    // ================= phase B =================
    for (int kt = 0; kt < NKT; kt++) {
        CPW_ITER(kt);                 // K(kt) and V(kt) complete
        __syncthreads();
        const uint32_t kb = sb + ((kt & 1) ? KB1 : KB0) + koff;
        uint4* pt = pbase + (size_t)kt * 8 * 256;

        #pragma unroll
        for (int c = 0; c < 8; c++) {
            float a0[4] = {0.f,0.f,0.f,0.f}, a1[4] = {0.f,0.f,0.f,0.f};
            #pragma unroll
            for (int ks = 0; ks < 4; ks++) {
                uint32_t b[4];
                ldsm4(kb + (uint32_t)((c * 16 * PH + ks * 16) * 2), b);
                mmah(a0, aq[ks], b[0], b[1]);
                mmah(a1, aq[ks], b[2], b[3]);
            }
            float e00 = ex2f(a0[0]), e01 = ex2f(a0[1]);
            float e02 = ex2f(a0[2]), e03 = ex2f(a0[3]);
            float e10 = ex2f(a1[0]), e11 = ex2f(a1[1]);
            float e12 = ex2f(a1[2]), e13 = ex2f(a1[3]);
            rs0 += e00 + e01 + e10 + e11;
            rs1 += e02 + e03 + e12 + e13;
            uint4 pk;
            pk.x = packh2(e00, e01);
            pk.y = packh2(e02, e03);
            pk.z = packh2(e10, e11);
            pk.w = packh2(e12, e13);
            stg_cs_u4(&pt[c * 256], pk);

            // AV immediately with the same packed p (single fp16 rounding)
            uint32_t ap[4] = {pk.x, pk.y, pk.z, pk.w};
            #pragma unroll
            for (int d2 = 0; d2 < 4; d2++) {
                uint32_t bv[4];
                ldsm4t(voff + (uint32_t)(c * 16 * PH * 2 + d2 * 32), bv);
                mmah(oacc[2*d2],     ap, bv[0], bv[1]);
                mmah(oacc[2*d2 + 1], ap, bv[2], bv[3]);
            }
        }
        __syncthreads();              // all warps done with VB and KB(kt)
        if (kt + 1 < NKT) { fetch_tile(sb + VB, vg + (size_t)(kt + 1) * 128 * D_, tid); CPC(); }
        if (kt + 2 < NKT) { fetch_tile(sb + ((kt & 1) ? KB1 : KB0),
                                       kg + (size_t)(kt + 2) * 128 * D_, tid); CPC(); }
    }

    // ---- rowsum reduce (quad) and out epilogue (frees oacc before phase C) ----
    rs0 += __shfl_xor_sync(0xFFFFFFFF, rs0, 1);
    rs0 += __shfl_xor_sync(0xFFFFFFFF, rs0, 2);
    rs1 += __shfl_xor_sync(0xFFFFFFFF, rs1, 1);
    rs1 += __shfl_xor_sync(0xFFFFFFFF, rs1, 2);
    const float inv0 = 1.0f / rs0;
    const float inv1 = 1.0f / rs1;

    float* orow0 = out + ((size_t)(bh * S_ + qrow0 + m0 + (lane >> 2))) * D_
                   + (lane & 3) * 2;
    float* orow1 = orow0 + (size_t)8 * D_;
    #pragma unroll
    for (int dt = 0; dt < 8; dt++) {
        *(float2*)(orow0 + dt * 8) = make_float2(oacc[dt][0] * inv0,
                                                 oacc[dt][1] * inv0);
        *(float2*)(orow1 + dt * 8) = make_float2(oacc[dt][2] * inv1,
                                                 oacc[dt][3] * inv1);
    }

    // ============ phase C: pure normalize stream (no smem, no syncs) ============
    for (int kt = 0; kt < NKT; kt++) {
        const uint4* pt = pbase + (size_t)kt * 8 * 256;
        uint4 pk[8];
        #pragma unroll
        for (int c = 0; c < 8; c++) pk[c] = ldg_cs_u4(&pt[c * 256]);  // MLP = 8

        float* arow0 = attn + ((size_t)(bh * S_ + qrow0 + m0 + (lane >> 2))) * S_
                       + kt * TK + (lane & 3) * 2;
        float* arow1 = arow0 + (size_t)8 * S_;
        #pragma unroll
        for (int c = 0; c < 8; c++) {
            float2 f0 = __half22float2(*(__half2*)&pk[c].x);
            float2 f1 = __half22float2(*(__half2*)&pk[c].y);
            float2 f2 = __half22float2(*(__half2*)&pk[c].z);
            float2 f3 = __half22float2(*(__half2*)&pk[c].w);
            stg_cs_f2(arow0 + c * 16,     f0.x * inv0, f0.y * inv0);
            stg_cs_f2(arow1 + c * 16,     f1.x * inv1, f1.y * inv1);
            stg_cs_f2(arow0 + c * 16 + 8, f2.x * inv0, f2.y * inv0);
            stg_cs_f2(arow1 + c * 16 + 8, f3.x * inv1, f3.y * inv1);
        }
    }
}

extern "C" void kernel_launch(void* const* d_in, const int* in_sizes, int n_in,
                              void* d_out, int out_size)
{
    const float* q = (const float*)d_in[0];
    const float* k = (const float*)d_in[1];
    const float* v = (const float*)d_in[2];
    float* out  = (float*)d_out;                    // [B,H,S,D]
    float* attn = out + (size_t)NBH * S_ * D_;      // [B,H,S,S]

    dim3 gc(NELEM / (256 * 4), 3);
    conv16<<<gc, 256>>>(q, k, v);

    dim3 g(NQT, NBH);
    cudaFuncSetAttribute(attn_fused,
                         cudaFuncAttributeMaxDynamicSharedMemorySize, SMEM_BYTES);
    attn_fused<<<g, 256, SMEM_BYTES>>>(out, attn);
}